// round 9
// baseline (speedup 1.0000x reference)
#include <cuda_runtime.h>
#include <cuda_bf16.h>
#include <cstdint>

// ---------------------------------------------------------------------------
// Problem: B=128, F=1024, W=32, H=64.  softmax over a size-1 axis == 1, so the
// attention branch is dead; model = plain LSTM, output = CELL state per step.
//   G[m][n] = sum_k x[b][k][t] * Wx[k][n] + b_lstm[n],  m = b*32 + t
// GEMM: bf16 mma.sync, 3-pass hi/lo compensation, cp.async 3-stage pipeline.
// ---------------------------------------------------------------------------
#define B_   128
#define F_   1024
#define W_   32
#define H_   64
#define G4   256
#define PADK 40                  // smem row stride in bf16 (80B): conflict-free

__device__ float          g_G [B_ * W_ * G4];    // gate preactivations, 4 MB
__device__ __nv_bfloat16  g_xh[B_ * W_ * F_];    // x^T hi  [m][k], 8 MB
__device__ __nv_bfloat16  g_xl[B_ * W_ * F_];    // x^T lo
__device__ __nv_bfloat16  g_wh[G4 * F_];         // Wx^T hi [n][k], 512 KB
__device__ __nv_bfloat16  g_wl[G4 * F_];         // Wx^T lo

// ---- helpers ---------------------------------------------------------------
__device__ __forceinline__ uint32_t smaddr(const void* p) {
    return (uint32_t)__cvta_generic_to_shared(p);
}
__device__ __forceinline__ void split2(float a, float b, uint32_t& hi, uint32_t& lo) {
    uint32_t ua = __float_as_uint(a), ub = __float_as_uint(b);
    hi = (ua >> 16) | (ub & 0xFFFF0000u);                   // truncated bf16 pair
    float la = a - __uint_as_float(ua & 0xFFFF0000u);
    float lb = b - __uint_as_float(ub & 0xFFFF0000u);
    __nv_bfloat162 p = __floats2bfloat162_rn(la, lb);
    lo = *reinterpret_cast<uint32_t*>(&p);
}
__device__ __forceinline__ void mma_bf16(float* c,
                                         const uint32_t* a, uint32_t b0, uint32_t b1) {
    asm volatile(
        "mma.sync.aligned.m16n8k16.row.col.f32.bf16.bf16.f32 "
        "{%0,%1,%2,%3}, {%4,%5,%6,%7}, {%8,%9}, {%0,%1,%2,%3};\n"
        : "+f"(c[0]), "+f"(c[1]), "+f"(c[2]), "+f"(c[3])
        : "r"(a[0]), "r"(a[1]), "r"(a[2]), "r"(a[3]), "r"(b0), "r"(b1));
}
__device__ __forceinline__ void ldsm4(uint32_t* r, uint32_t addr) {
    asm volatile("ldmatrix.sync.aligned.m8n8.x4.shared.b16 {%0,%1,%2,%3}, [%4];"
                 : "=r"(r[0]), "=r"(r[1]), "=r"(r[2]), "=r"(r[3]) : "r"(addr));
}
__device__ __forceinline__ void cpa16(uint32_t dst, const void* src) {
    asm volatile("cp.async.cg.shared.global [%0], [%1], 16;" :: "r"(dst), "l"(src));
}
#define CPA_COMMIT() asm volatile("cp.async.commit_group;" ::: "memory")
#define CPA_WAIT1()  asm volatile("cp.async.wait_group 1;" ::: "memory")

// ---------------------------------------------------------------------------
// Kernel 0a: x [B][F][W] -> g_xh/g_xl [m=b*32+t][k=f]  (transpose + split)
// ---------------------------------------------------------------------------
__global__ __launch_bounds__(256) void split_x(const float* __restrict__ x) {
    __shared__ float tile[128][33];
    const int tid = threadIdx.x;
    const int b   = blockIdx.y;
    const int f0  = blockIdx.x * 128;
#pragma unroll
    for (int i = 0; i < 4; i++) {
        int idx = i * 256 + tid;
        int f = idx >> 3, tq = idx & 7;
        float4 v = *reinterpret_cast<const float4*>(x + ((size_t)b * F_ + f0 + f) * W_ + tq * 4);
        tile[f][tq * 4 + 0] = v.x; tile[f][tq * 4 + 1] = v.y;
        tile[f][tq * 4 + 2] = v.z; tile[f][tq * 4 + 3] = v.w;
    }
    __syncthreads();
    const int t  = tid >> 3;
    const int fo = (tid & 7) * 16;
    uint32_t hi[8], lo[8];
#pragma unroll
    for (int p = 0; p < 8; p++)
        split2(tile[fo + 2 * p][t], tile[fo + 2 * p + 1][t], hi[p], lo[p]);
    size_t dst = ((size_t)b * W_ + t) * F_ + f0 + fo;
    *reinterpret_cast<uint4*>(g_xh + dst)     = make_uint4(hi[0], hi[1], hi[2], hi[3]);
    *reinterpret_cast<uint4*>(g_xh + dst + 8) = make_uint4(hi[4], hi[5], hi[6], hi[7]);
    *reinterpret_cast<uint4*>(g_xl + dst)     = make_uint4(lo[0], lo[1], lo[2], lo[3]);
    *reinterpret_cast<uint4*>(g_xl + dst + 8) = make_uint4(lo[4], lo[5], lo[6], lo[7]);
}

// ---------------------------------------------------------------------------
// Kernel 0b: Wx [K][N] -> g_wh/g_wl [n][k]  (transpose + split)
// ---------------------------------------------------------------------------
__global__ __launch_bounds__(256) void split_w(const float* __restrict__ Wx) {
    __shared__ float tile[64][65];
    const int tid = threadIdx.x;
    const int k0  = blockIdx.x * 64;
    const int n0  = blockIdx.y * 64;
#pragma unroll
    for (int i = 0; i < 4; i++) {
        int idx = i * 256 + tid;
        int k = idx >> 4, nq = idx & 15;
        float4 v = *reinterpret_cast<const float4*>(Wx + (size_t)(k0 + k) * G4 + n0 + nq * 4);
        tile[k][nq * 4 + 0] = v.x; tile[k][nq * 4 + 1] = v.y;
        tile[k][nq * 4 + 2] = v.z; tile[k][nq * 4 + 3] = v.w;
    }
    __syncthreads();
    const int n  = tid >> 2;
    const int ko = (tid & 3) * 16;
    uint32_t hi[8], lo[8];
#pragma unroll
    for (int p = 0; p < 8; p++)
        split2(tile[ko + 2 * p][n], tile[ko + 2 * p + 1][n], hi[p], lo[p]);
    size_t dst = (size_t)(n0 + n) * F_ + k0 + ko;
    *reinterpret_cast<uint4*>(g_wh + dst)     = make_uint4(hi[0], hi[1], hi[2], hi[3]);
    *reinterpret_cast<uint4*>(g_wh + dst + 8) = make_uint4(hi[4], hi[5], hi[6], hi[7]);
    *reinterpret_cast<uint4*>(g_wl + dst)     = make_uint4(lo[0], lo[1], lo[2], lo[3]);
    *reinterpret_cast<uint4*>(g_wl + dst + 8) = make_uint4(lo[4], lo[5], lo[6], lo[7]);
}

// ---------------------------------------------------------------------------
// Kernel 1: mma.sync GEMM, 3-pass hi/lo, ldmatrix fragments, cp.async ring.
// CTA tile 128x64, BK=32, grid (32,4), 256 threads = 8 warps (2m x 4n),
// warp tile m64 x n16. 3-stage cp.async pipeline: global latency never on the
// critical path (stage kt+2 loads overlap compute of kt and kt+1).
// ---------------------------------------------------------------------------
#define AH_E  0
#define AL_E  (128 * PADK)
#define BH_E  (2 * 128 * PADK)
#define BL_E  (2 * 128 * PADK + 64 * PADK)
#define BUFE  (2 * 128 * PADK + 2 * 64 * PADK)      // 15360 bf16 = 30720 B
#define NKT   (F_ / 32)                             // 32 k-tiles
#define GEMM_SMEM (3 * BUFE * 2)                    // 92160 B

__global__ __launch_bounds__(256, 1)
void gate_gemm_mma(const float* __restrict__ bl) {
    extern __shared__ __nv_bfloat16 sm[];

    const int tid  = threadIdx.x;
    const int warp = tid >> 5;
    const int lane = tid & 31;
    const int wm   = (warp >> 2) * 64;      // 0 or 64
    const int wn   = (warp & 3) * 16;       // 0,16,32,48
    const int g    = lane >> 2;
    const int tq   = lane & 3;
    const int m0   = blockIdx.x * 128;
    const int n0   = blockIdx.y * 64;

    // ldmatrix per-lane source rows (element offsets into a buffer)
    const int arow = wm + (lane & 15);
    const int akh  = ((lane >> 4) & 1) * 8;               // A k-half
    const int brow = wn + (lane & 7) + ((lane >> 4) & 1) * 8;
    const int bkh  = ((lane >> 3) & 1) * 8;               // B k-half
    const uint32_t sb = smaddr(sm);
    const uint32_t aAh = sb + 2 * (AH_E + arow * PADK + akh);
    const uint32_t aAl = sb + 2 * (AL_E + arow * PADK + akh);
    const uint32_t aBh = sb + 2 * (BH_E + brow * PADK + bkh);
    const uint32_t aBl = sb + 2 * (BL_E + brow * PADK + bkh);

    // staging maps (cp.async 16B x6 per thread per stage)
    const int srow = tid >> 2;              // 0..63
    const int sv   = tid & 3;               // 16B vec within 64B row
    const uint4* pxh0 = reinterpret_cast<const uint4*>(g_xh + (size_t)(m0 + srow) * F_) + sv;
    const uint4* pxh1 = reinterpret_cast<const uint4*>(g_xh + (size_t)(m0 + 64 + srow) * F_) + sv;
    const uint4* pxl0 = reinterpret_cast<const uint4*>(g_xl + (size_t)(m0 + srow) * F_) + sv;
    const uint4* pxl1 = reinterpret_cast<const uint4*>(g_xl + (size_t)(m0 + 64 + srow) * F_) + sv;
    const uint4* pwh  = reinterpret_cast<const uint4*>(g_wh + (size_t)(n0 + srow) * F_) + sv;
    const uint4* pwl  = reinterpret_cast<const uint4*>(g_wl + (size_t)(n0 + srow) * F_) + sv;
    const uint32_t dA0 = sb + 2 * (AH_E + srow * PADK) + sv * 16;
    const uint32_t dA1 = sb + 2 * (AH_E + (64 + srow) * PADK) + sv * 16;
    const uint32_t dL0 = sb + 2 * (AL_E + srow * PADK) + sv * 16;
    const uint32_t dL1 = sb + 2 * (AL_E + (64 + srow) * PADK) + sv * 16;
    const uint32_t dBh = sb + 2 * (BH_E + srow * PADK) + sv * 16;
    const uint32_t dBl = sb + 2 * (BL_E + srow * PADK) + sv * 16;

    auto issue = [&](int s, int bufid) {
        if (s < NKT) {
            const uint32_t bo = (uint32_t)(2 * bufid * BUFE);
            const int o = s * 4;
            cpa16(dA0 + bo, pxh0 + o);
            cpa16(dA1 + bo, pxh1 + o);
            cpa16(dL0 + bo, pxl0 + o);
            cpa16(dL1 + bo, pxl1 + o);
            cpa16(dBh + bo, pwh + o);
            cpa16(dBl + bo, pwl + o);
        }
        CPA_COMMIT();
    };

    float acc[4][2][4];
#pragma unroll
    for (int mt = 0; mt < 4; mt++)
#pragma unroll
        for (int nt = 0; nt < 2; nt++)
#pragma unroll
            for (int r = 0; r < 4; r++) acc[mt][nt][r] = 0.f;

    issue(0, 0);
    issue(1, 1);

    int bufid = 0, nxt = 2;
    for (int kt = 0; kt < NKT; kt++) {
        CPA_WAIT1();                 // this thread's stage-kt copies done
        __syncthreads();             // everyone's copies visible; prior reads
                                     // of the buffer we're about to refill done
        issue(kt + 2, nxt);

        const uint32_t bofs = (uint32_t)(2 * bufid * BUFE);
#pragma unroll
        for (int ks = 0; ks < 32; ks += 16) {
            uint32_t bh[4], blo[4];
            ldsm4(bh,  aBh + bofs + 2 * ks);
            ldsm4(blo, aBl + bofs + 2 * ks);
#pragma unroll
            for (int mt = 0; mt < 4; mt++) {
                uint32_t ah[4], al[4];
                ldsm4(ah, aAh + bofs + 2 * (mt * 16 * PADK + ks));
                ldsm4(al, aAl + bofs + 2 * (mt * 16 * PADK + ks));
                mma_bf16(acc[mt][0], ah, bh[0],  bh[1]);
                mma_bf16(acc[mt][1], ah, bh[2],  bh[3]);
                mma_bf16(acc[mt][0], al, bh[0],  bh[1]);
                mma_bf16(acc[mt][1], al, bh[2],  bh[3]);
                mma_bf16(acc[mt][0], ah, blo[0], blo[1]);
                mma_bf16(acc[mt][1], ah, blo[2], blo[3]);
            }
        }
        bufid = (bufid == 2) ? 0 : bufid + 1;
        nxt   = (nxt   == 2) ? 0 : nxt + 1;
    }

    // epilogue: bias + store (c0,c1 at row g, c2,c3 at g+8)
#pragma unroll
    for (int nt = 0; nt < 2; nt++) {
        int n = n0 + wn + nt * 8 + 2 * tq;
        float2 bias = *reinterpret_cast<const float2*>(&bl[n]);
#pragma unroll
        for (int mt = 0; mt < 4; mt++) {
            int m = m0 + wm + mt * 16 + g;
            float2 o0, o1;
            o0.x = acc[mt][nt][0] + bias.x;  o0.y = acc[mt][nt][1] + bias.y;
            o1.x = acc[mt][nt][2] + bias.x;  o1.y = acc[mt][nt][3] + bias.y;
            *reinterpret_cast<float2*>(&g_G[(size_t)m * G4 + n])       = o0;
            *reinterpret_cast<float2*>(&g_G[(size_t)(m + 8) * G4 + n]) = o1;
        }
    }
}

// ---------------------------------------------------------------------------
// Kernel 2: LSTM recurrence. 1 CTA/batch, 256 threads = 8 warps.
// Lane l of warp w: dot for (gate = l>>3, unit = 8w + (l&7)); G in smem;
// per-lane own-gate activation then shuffle; predicated asm stores (no
// BSSY/BSYNC); one __syncthreads per step.
// ---------------------------------------------------------------------------
__device__ __forceinline__ unsigned long long pk2(float lo, float hi) {
    unsigned long long r;
    asm("mov.b64 %0, {%1, %2};" : "=l"(r) : "f"(lo), "f"(hi));
    return r;
}
__device__ __forceinline__ unsigned long long fma2_(unsigned long long a,
                                                    unsigned long long b,
                                                    unsigned long long c) {
    unsigned long long d;
    asm("fma.rn.f32x2 %0, %1, %2, %3;" : "=l"(d) : "l"(a), "l"(b), "l"(c));
    return d;
}
__device__ __forceinline__ void upk2(float& lo, float& hi, unsigned long long v) {
    asm("mov.b64 {%0, %1}, %2;" : "=f"(lo), "=f"(hi) : "l"(v));
}

__global__ __launch_bounds__(256, 1)
void lstm_rec(const float* __restrict__ Wh, float* __restrict__ out) {
    const int b   = blockIdx.x;
    const int tid = threadIdx.x;
    const int w   = tid >> 5;
    const int l   = tid & 31;
    const int u   = 8 * w + (l & 7);
    const int gq  = l >> 3;
    const int n   = gq * 64 + u;

    __shared__ __align__(16) float Gsh[W_ * G4];     // 32 KB
    __shared__ __align__(16) float hbuf[2][H_];

    // activation: y = 1/(1+e^{fa*v}); act = fb*y + fc  (tanh for gate 2)
    const float fa = (gq == 2) ? -2.0f : -1.0f;
    const float fb = (gq == 2) ?  2.0f :  1.0f;
    const float fc = (gq == 2) ? -1.0f :  0.0f;

    unsigned long long wh2[32];
#pragma unroll
    for (int kk = 0; kk < 32; kk++)
        wh2[kk] = pk2(Wh[(2 * kk) * G4 + n], Wh[(2 * kk + 1) * G4 + n]);

    {   // stage this batch's G slice into smem (coalesced)
        const float4* src = reinterpret_cast<const float4*>(g_G + (size_t)b * W_ * G4);
        float4* dst = reinterpret_cast<float4*>(Gsh);
#pragma unroll
        for (int j = 0; j < 8; j++) dst[j * 256 + tid] = src[j * 256 + tid];
    }
    if (tid < H_) hbuf[0][tid] = 0.0f;
    float c = 0.0f;
    __syncthreads();

    const uint32_t hB = smaddr(hbuf) + 4u * u;       // +256B for buffer 1
    float* outp = out + (size_t)b * (W_ * H_) + u;

    int p = 0;
#pragma unroll 1
    for (int t = 0; t < W_; t++) {
        const unsigned long long* h2 =
            reinterpret_cast<const unsigned long long*>(hbuf[p]);

        unsigned long long a0 = pk2(Gsh[t * G4 + n], 0.0f);
        unsigned long long a1 = 0ull, a2 = 0ull, a3 = 0ull;
#pragma unroll
        for (int kk = 0; kk < 8; kk++) {
            a0 = fma2_(h2[kk],      wh2[kk],      a0);
            a1 = fma2_(h2[8 + kk],  wh2[8 + kk],  a1);
            a2 = fma2_(h2[16 + kk], wh2[16 + kk], a2);
            a3 = fma2_(h2[24 + kk], wh2[24 + kk], a3);
        }
        float s0, s1, s2, s3, s4, s5, s6, s7;
        upk2(s0, s1, a0); upk2(s2, s3, a1);
        upk2(s4, s5, a2); upk2(s6, s7, a3);
        float v = ((s0 + s1) + (s2 + s3)) + ((s4 + s5) + (s6 + s7));

        float y   = 1.0f / (1.0f + __expf(fa * v));
        float act = fmaf(fb, y, fc);

        int src = l & 7;
        float ig = __shfl_sync(0xFFFFFFFFu, act, src);
        float fg = __shfl_sync(0xFFFFFFFFu, act, src + 8);
        float gg = __shfl_sync(0xFFFFFFFFu, act, src + 16);
        float og = __shfl_sync(0xFFFFFFFFu, act, src + 24);

        c = fg * c + ig * gg;
        float tc = fmaf(2.0f, 1.0f / (1.0f + __expf(-2.0f * c)), -1.0f);  // tanh(c)
        float hn = og * tc;

        // predicated stores (no BSSY/BSYNC): lanes 0..7 write h and out
        uint32_t haddr = hB + (uint32_t)((p ^ 1) << 8);
        float* op = outp + t * H_;
        asm volatile(
            "{ .reg .pred pp; setp.lt.s32 pp, %0, 8;\n\t"
            "@pp st.shared.f32 [%1], %2;\n\t"
            "@pp st.global.f32 [%3], %4; }"
            :: "r"(l), "r"(haddr), "f"(hn), "l"(op), "f"(c) : "memory");

        p ^= 1;
        __syncthreads();
    }
}

// ---------------------------------------------------------------------------
// Launch
// ---------------------------------------------------------------------------
extern "C" void kernel_launch(void* const* d_in, const int* in_sizes, int n_in,
                              void* d_out, int out_size) {
    const float* x   = (const float*)d_in[0];   // [B, F, W]
    // d_in[1..5] (attention params) are dead: softmax over size-1 axis == 1.
    const float* Wx  = (const float*)d_in[6];   // [F, 4H]
    const float* Wh  = (const float*)d_in[7];   // [H, 4H]
    const float* blm = (const float*)d_in[8];   // [4H]
    float* out = (float*)d_out;                 // [B, W, H]

    cudaFuncSetAttribute(gate_gemm_mma,
                         cudaFuncAttributeMaxDynamicSharedMemorySize, GEMM_SMEM);

    split_x<<<dim3(8, 128), 256>>>(x);
    split_w<<<dim3(16, 4), 256>>>(Wx);
    gate_gemm_mma<<<dim3(32, 4), 256, GEMM_SMEM>>>(blm);
    lstm_rec<<<B_, 256>>>(Wh, out);
}